// round 8
// baseline (speedup 1.0000x reference)
#include <cuda_runtime.h>
#include <math.h>

#define NE     16
#define NPTS   524288
#define TPB    256
#define PPT    2
#define NBLK   (NPTS / (TPB * PPT))   // 1024

// ---------------------------------------------------------------------------
// helpers
// ---------------------------------------------------------------------------
__device__ __forceinline__ float fast_sig(float x)
{
    return __fdividef(1.f, 1.f + __expf(-x));
}

// Branch-free atan2, abs err ~1e-5. theta = atan2(rxy, z) == acos(z/rho).
__device__ __forceinline__ float atan2f_fast(float y, float x)
{
    float ax = fabsf(x), ay = fabsf(y);
    float mx = fmaxf(ax, ay);
    float mn = fminf(ax, ay);
    float a  = __fdividef(mn, mx);
    float s  = a * a;
    float r  = fmaf(s, -0.0117212f, 0.05265332f);
    r = fmaf(s, r, -0.11643287f);
    r = fmaf(s, r,  0.19354346f);
    r = fmaf(s, r, -0.33262347f);
    r = fmaf(s, r,  0.99997726f);
    r = r * a;
    r = (ay > ax) ? 1.57079632679f - r : r;
    r = (x < 0.f) ? 3.14159265359f - r : r;
    return copysignf(r, y);
}

// ---------------------------------------------------------------------------
// Fused kernel. Each block folds the tiny MoE weights into a packed blob in
// its own shared memory, then streams 512 points (2 per thread).
//
// Blob layout (float4 units):
//   sBlob[0..15]   gate[e] = {Wg[0][e],Wg[1][e],Wg[2][e],Wg[3][e]}
//   sBlob[16..19]  bg (16 floats)
//   sBlob[20+e*11 + r], r=0:(cx,cy,cz,tb1) r=1:(tb2,-,-,-)
//                       r=2..8: M rows rho,phi,theta,cos,sin,silu(cos),silu(sin)
//                       r=9: bias(bf)  r=10: pad
// ---------------------------------------------------------------------------
__global__ __launch_bounds__(TPB, 5)
void moe_fused_kernel(const float4* __restrict__ xyzt,
                      const float*  __restrict__ Wg,
                      const float*  __restrict__ bg,
                      const float*  __restrict__ proj,
                      const float*  __restrict__ center,
                      const float*  __restrict__ tb1,
                      const float*  __restrict__ tb2,
                      const float*  __restrict__ W1,
                      const float*  __restrict__ Wf,
                      const float*  __restrict__ bf,
                      float4*       __restrict__ out)
{
    __shared__ float4 sWf4[NE * 32];   // Wf rows as float4 (E,32,4)
    __shared__ float  sProj[NE * 24];  // (E,3,8)
    __shared__ float4 sP4[NE * 12];    // P[e][p][:] = W1 row . Wf cols
    __shared__ float4 sBlob[196];

    const int t = threadIdx.x;

    // --- stage A: stage Wf + proj into smem (coalesced) ---
    sWf4[t]       = ((const float4*)Wf)[t];
    sWf4[t + 256] = ((const float4*)Wf)[t + 256];
    if (t < 96) ((float4*)sProj)[t] = ((const float4*)proj)[t];
    __syncthreads();

    // --- stage B: P[e,p,:] = W1[e,p,:] @ Wf[e]  (192 dots of length 32) ---
    if (t < NE * 12) {
        int e = t / 12;
        const float4* w1r = (const float4*)(W1 + t * 32);
        const float4* wfe = sWf4 + e * 32;
        float4 acc = make_float4(0.f, 0.f, 0.f, 0.f);
        #pragma unroll
        for (int hh = 0; hh < 8; ++hh) {
            float4 a = w1r[hh];
            float4 b;
            b = wfe[hh*4+0]; acc.x=fmaf(a.x,b.x,acc.x); acc.y=fmaf(a.x,b.y,acc.y); acc.z=fmaf(a.x,b.z,acc.z); acc.w=fmaf(a.x,b.w,acc.w);
            b = wfe[hh*4+1]; acc.x=fmaf(a.y,b.x,acc.x); acc.y=fmaf(a.y,b.y,acc.y); acc.z=fmaf(a.y,b.z,acc.z); acc.w=fmaf(a.y,b.w,acc.w);
            b = wfe[hh*4+2]; acc.x=fmaf(a.z,b.x,acc.x); acc.y=fmaf(a.z,b.y,acc.y); acc.z=fmaf(a.z,b.z,acc.z); acc.w=fmaf(a.z,b.w,acc.w);
            b = wfe[hh*4+3]; acc.x=fmaf(a.w,b.x,acc.x); acc.y=fmaf(a.w,b.y,acc.y); acc.z=fmaf(a.w,b.z,acc.z); acc.w=fmaf(a.w,b.w,acc.w);
        }
        sP4[t] = acc;
    }
    __syncthreads();

    // --- stage C: assemble blob (16 threads, one per expert) ---
    if (t < NE) {
        int e = t;
        sBlob[e] = make_float4(Wg[e], Wg[16+e], Wg[32+e], Wg[48+e]);
        ((float*)(sBlob + 16))[e] = bg[e];
        float4* R = sBlob + 20 + e * 11;
        R[0] = make_float4(center[e*3], center[e*3+1], center[e*3+2], tb1[e]);
        R[1] = make_float4(tb2[e], 0.f, 0.f, 0.f);
        #pragma unroll
        for (int i = 0; i < 3; ++i) {           // fold proj into rho/phi/theta rows
            float4 acc = make_float4(0.f, 0.f, 0.f, 0.f);
            const float* pe = sProj + e*24 + i*8;
            #pragma unroll
            for (int p = 0; p < 8; ++p) {
                float4 b = sP4[e*12 + p];
                float  s = pe[p];
                acc.x=fmaf(s,b.x,acc.x); acc.y=fmaf(s,b.y,acc.y);
                acc.z=fmaf(s,b.z,acc.z); acc.w=fmaf(s,b.w,acc.w);
            }
            R[2 + i] = acc;
        }
        #pragma unroll
        for (int m = 0; m < 4; ++m)             // temb rows
            R[5 + m] = sP4[e*12 + 8 + m];
        R[9] = ((const float4*)bf)[e];          // bias row
    }
    __syncthreads();

    // --- stage D: stream points, 2 per thread ---
    const float4* gate = sBlob;
    const float*  sbg  = (const float*)(sBlob + 16);
    const int base = blockIdx.x * (TPB * PPT) + t;

    float4 pt0 = xyzt[base];
    float4 pt1 = xyzt[base + TPB];

    #pragma unroll
    for (int pp = 0; pp < PPT; ++pp) {
        float4 p = pp ? pt1 : pt0;

        // gating: top-2 of 16 via FMNMX chain, expert index in low mantissa bits
        float b0 = -3.0e38f, b1 = -3.0e38f;
        #pragma unroll
        for (int e = 0; e < NE; ++e) {
            float4 g = gate[e];
            float l = fmaf(p.x, g.x, fmaf(p.y, g.y, fmaf(p.z, g.z, fmaf(p.w, g.w, sbg[e]))));
            l = __int_as_float((__float_as_int(l) & 0xFFFFFFF0) | e);
            b1 = fmaxf(b1, fminf(b0, l));
            b0 = fmaxf(b0, l);
        }
        int e0 = __float_as_int(b0) & 15;
        int e1 = __float_as_int(b1) & 15;
        float w0 = fast_sig(b0 - b1);           // softmax over 2 = sigmoid(diff)

        float4 v0, v1;

        #pragma unroll
        for (int k = 0; k < 2; ++k) {
            int e = k ? e1 : e0;
            const float4* R = sBlob + 20 + e * 11;

            float4 A   = R[0];
            float tb2v = R[1].x;

            float xc0 = p.x - A.x;
            float xc1 = p.y - A.y;
            float xc2 = p.z - A.z;
            float r2xy = fmaf(xc0, xc0, xc1 * xc1);
            float rxy  = sqrtf(r2xy);
            float rho  = sqrtf(fmaf(xc2, xc2, r2xy));
            float phi   = atan2f_fast(xc1, xc0);
            float theta = atan2f_fast(rxy, xc2);

            float ct = __cosf(p.w + A.w);
            float st = __sinf(p.w + tb2v);
            float sc = ct * fast_sig(ct);
            float ss = st * fast_sig(st);

            float4 v = R[9];
            float4 m;
            m = R[2]; v.x=fmaf(rho,  m.x,v.x); v.y=fmaf(rho,  m.y,v.y); v.z=fmaf(rho,  m.z,v.z); v.w=fmaf(rho,  m.w,v.w);
            m = R[3]; v.x=fmaf(phi,  m.x,v.x); v.y=fmaf(phi,  m.y,v.y); v.z=fmaf(phi,  m.z,v.z); v.w=fmaf(phi,  m.w,v.w);
            m = R[4]; v.x=fmaf(theta,m.x,v.x); v.y=fmaf(theta,m.y,v.y); v.z=fmaf(theta,m.z,v.z); v.w=fmaf(theta,m.w,v.w);
            m = R[5]; v.x=fmaf(ct,   m.x,v.x); v.y=fmaf(ct,   m.y,v.y); v.z=fmaf(ct,   m.z,v.z); v.w=fmaf(ct,   m.w,v.w);
            m = R[6]; v.x=fmaf(st,   m.x,v.x); v.y=fmaf(st,   m.y,v.y); v.z=fmaf(st,   m.z,v.z); v.w=fmaf(st,   m.w,v.w);
            m = R[7]; v.x=fmaf(sc,   m.x,v.x); v.y=fmaf(sc,   m.y,v.y); v.z=fmaf(sc,   m.z,v.z); v.w=fmaf(sc,   m.w,v.w);
            m = R[8]; v.x=fmaf(ss,   m.x,v.x); v.y=fmaf(ss,   m.y,v.y); v.z=fmaf(ss,   m.z,v.z); v.w=fmaf(ss,   m.w,v.w);

            if (k == 0) v0 = v; else v1 = v;
        }

        // o = v1 + w0*(v0 - v1)   (uses w0 + w1 = 1)
        float4 o;
        o.x = fmaf(w0, v0.x - v1.x, v1.x);
        o.y = fmaf(w0, v0.y - v1.y, v1.y);
        o.z = fmaf(w0, v0.z - v1.z, v1.z);
        o.w = fmaf(w0, v0.w - v1.w, v1.w);

        out[base + pp * TPB] = o;
    }
}

// ---------------------------------------------------------------------------
extern "C" void kernel_launch(void* const* d_in, const int* in_sizes, int n_in,
                              void* d_out, int out_size)
{
    const float* xyzt   = (const float*)d_in[0];
    const float* Wg     = (const float*)d_in[1];
    const float* bg     = (const float*)d_in[2];
    const float* proj   = (const float*)d_in[3];
    const float* center = (const float*)d_in[4];
    const float* tb1    = (const float*)d_in[5];
    const float* tb2    = (const float*)d_in[6];
    const float* W1     = (const float*)d_in[7];
    const float* Wf     = (const float*)d_in[8];
    const float* bf     = (const float*)d_in[9];

    moe_fused_kernel<<<NBLK, TPB>>>((const float4*)xyzt, Wg, bg, proj, center,
                                    tb1, tb2, W1, Wf, bf, (float4*)d_out);
}

// round 10
// speedup vs baseline: 1.3244x; 1.3244x over previous
#include <cuda_runtime.h>
#include <math.h>

#define NE     16
#define NPTS   524288
#define TPB    256

// Packed parameter blob (784 floats = 196 float4), produced by fold_kernel:
//   [0..15]   Wg verbatim (4x16 row-major): float4 #(c*4+j) = Wg[c][4j..4j+3]
//   [16..19]  bg verbatim (16 floats)
//   [20+e*11 + r] expert record e (float offsets within record):
//       [0..3]  = cx, cy, cz, tb1
//       [4]     = tb2            ([5..7] pad = 0)
//       [8..35] = M rows (7x4): rho, phi, theta, cos, sin, silu(cos), silu(sin)
//       [36..39]= bias (bf[e])   ([40..43] pad = 0)
__device__ float4 g_R4[196];

// ---------------------------------------------------------------------------
// f32x2 packed-math helpers (sm_103a FFMA2 — only reachable via PTX)
// ---------------------------------------------------------------------------
typedef unsigned long long ull;
union F4U { float4 v; ull u[2]; };
union U64 { ull u; float2 f; };

__device__ __forceinline__ ull pack2(float lo, float hi)
{
    ull r; asm("mov.b64 %0, {%1, %2};" : "=l"(r) : "f"(lo), "f"(hi)); return r;
}
__device__ __forceinline__ ull ffma2(ull a, ull b, ull c)
{
    ull d; asm("fma.rn.f32x2 %0, %1, %2, %3;" : "=l"(d) : "l"(a), "l"(b), "l"(c)); return d;
}
__device__ __forceinline__ ull fmul2(ull a, ull b)
{
    ull d; asm("mul.rn.f32x2 %0, %1, %2;" : "=l"(d) : "l"(a), "l"(b)); return d;
}

// ---------------------------------------------------------------------------
// scalar helpers
// ---------------------------------------------------------------------------
__device__ __forceinline__ float fast_sig(float x)
{
    return __fdividef(1.f, 1.f + __expf(-x));
}
__device__ __forceinline__ float fast_sqrt(float x)
{
    float r; asm("sqrt.approx.f32 %0, %1;" : "=f"(r) : "f"(x)); return r;
}

// Branch-free atan2, abs err ~1e-5. theta = atan2(rxy, z) == acos(z/rho).
__device__ __forceinline__ float atan2f_fast(float y, float x)
{
    float ax = fabsf(x), ay = fabsf(y);
    float mx = fmaxf(ax, ay);
    float mn = fminf(ax, ay);
    float a  = __fdividef(mn, mx);
    float s  = a * a;
    float r  = fmaf(s, -0.0117212f, 0.05265332f);
    r = fmaf(s, r, -0.11643287f);
    r = fmaf(s, r,  0.19354346f);
    r = fmaf(s, r, -0.33262347f);
    r = fmaf(s, r,  0.99997726f);
    r = r * a;
    r = (ay > ax) ? 1.57079632679f - r : r;
    r = (x < 0.f) ? 3.14159265359f - r : r;
    return copysignf(r, y);
}

// ---------------------------------------------------------------------------
// Fold kernel: 16 blocks (one expert each) x 64 threads. No wide barriers,
// scalar global stores straight into g_R4. ~1us.
// ---------------------------------------------------------------------------
__global__ void fold_kernel(const float* __restrict__ Wg,     // (4,16)
                            const float* __restrict__ bg,     // (16)
                            const float* __restrict__ proj,   // (E,3,8)
                            const float* __restrict__ center, // (E,3)
                            const float* __restrict__ tb1,
                            const float* __restrict__ tb2,
                            const float* __restrict__ W1,     // (E,12,32)
                            const float* __restrict__ Wf,     // (E,32,4)
                            const float* __restrict__ bf)     // (E,4)
{
    const int e = blockIdx.x;
    const int t = threadIdx.x;
    __shared__ float sP[48];           // P[p][j] = W1[e,p,:] . Wf[e,:,j]

    if (t < 48) {
        int pi = t >> 2, j = t & 3;
        const float* W1r = W1 + (e * 12 + pi) * 32;
        const float* Wfc = Wf + e * 128 + j;
        float acc = 0.f;
        #pragma unroll
        for (int h = 0; h < 32; ++h) acc = fmaf(W1r[h], Wfc[h * 4], acc);
        sP[t] = acc;
    }
    // header copies from spare threads
    if (e == 0 && t >= 48)           g_R4[t - 48]      = ((const float4*)Wg)[t - 48];
    if (e == 1 && t >= 48 && t < 52) g_R4[16 + t - 48] = ((const float4*)bg)[t - 48];
    __syncthreads();

    float* R = (float*)(g_R4 + 20 + e * 11);
    if (t < 12) {                                   // rho/phi/theta rows: fold proj
        int i = t >> 2, j = t & 3;
        const float* pe = proj + e * 24 + i * 8;
        float acc = 0.f;
        #pragma unroll
        for (int p = 0; p < 8; ++p) acc = fmaf(pe[p], sP[p * 4 + j], acc);
        R[8 + i * 4 + j] = acc;
    } else if (t < 28) {                            // temb rows 3..6
        int m = t - 12;
        R[8 + (3 + (m >> 2)) * 4 + (m & 3)] = sP[(8 + (m >> 2)) * 4 + (m & 3)];
    } else if (t < 32) {                            // bias row
        R[36 + (t - 28)] = bf[e * 4 + (t - 28)];
    } else if (t < 35) {                            // center
        R[t - 32] = center[e * 3 + (t - 32)];
    } else if (t == 35) {
        R[3] = tb1[e];
    } else if (t == 36) {
        R[4] = tb2[e];
    }
}

// ---------------------------------------------------------------------------
// Main kernel: 1 point per thread, params from shared blob, FFMA2 math.
// ---------------------------------------------------------------------------
__global__ __launch_bounds__(TPB)
void moe_kernel(const float4* __restrict__ xyzt, float4* __restrict__ out)
{
    __shared__ float4 sB[196];
    const int t = threadIdx.x;
    if (t < 196) sB[t] = g_R4[t];
    __syncthreads();

    const int i = blockIdx.x * TPB + t;
    float4 p = xyzt[i];

    // ---- gating: 16 logits via FFMA2 (8 expert-pairs) ----
    ull pc0 = pack2(p.x, p.x), pc1 = pack2(p.y, p.y);
    ull pc2 = pack2(p.z, p.z), pc3 = pack2(p.w, p.w);

    U64 acc[8];
    #pragma unroll
    for (int j = 0; j < 4; ++j) {
        F4U b; b.v = sB[16 + j];
        acc[2 * j].u     = b.u[0];
        acc[2 * j + 1].u = b.u[1];
    }
    #pragma unroll
    for (int c = 0; c < 4; ++c) {
        ull pcv = (c == 0) ? pc0 : (c == 1) ? pc1 : (c == 2) ? pc2 : pc3;
        #pragma unroll
        for (int j = 0; j < 4; ++j) {
            F4U g; g.v = sB[c * 4 + j];
            acc[2 * j].u     = ffma2(pcv, g.u[0], acc[2 * j].u);
            acc[2 * j + 1].u = ffma2(pcv, g.u[1], acc[2 * j + 1].u);
        }
    }

    // top-2 via FMNMX chain, expert index in low 4 mantissa bits
    float b0 = -3.0e38f, b1 = -3.0e38f;
    #pragma unroll
    for (int e = 0; e < NE; ++e) {
        float l = (e & 1) ? acc[e >> 1].f.y : acc[e >> 1].f.x;
        l = __int_as_float((__float_as_int(l) & 0xFFFFFFF0) | e);
        b1 = fmaxf(b1, fminf(b0, l));
        b0 = fmaxf(b0, l);
    }
    int e0 = __float_as_int(b0) & 15;
    int e1 = __float_as_int(b1) & 15;
    float w0 = fast_sig(b0 - b1);               // softmax over 2 = sigmoid(diff)
    float w1 = 1.f - w0;

    F4U v0, v1;

    #pragma unroll
    for (int k = 0; k < 2; ++k) {
        int e = k ? e1 : e0;
        const float4* R = sB + 20 + e * 11;

        float4 A   = R[0];                      // cx, cy, cz, tb1
        float tb2v = R[1].x;

        float xc0 = p.x - A.x;
        float xc1 = p.y - A.y;
        float xc2 = p.z - A.z;
        float r2xy = fmaf(xc0, xc0, xc1 * xc1);
        float rxy  = fast_sqrt(r2xy);
        float rho  = fast_sqrt(fmaf(xc2, xc2, r2xy));
        float phi   = atan2f_fast(xc1, xc0);
        float theta = atan2f_fast(rxy, xc2);    // == acos(z/rho)

        float ct = __cosf(p.w + A.w);
        float st = __sinf(p.w + tb2v);
        float sc = ct * fast_sig(ct);
        float ss = st * fast_sig(st);

        ull f[7];
        f[0] = pack2(rho, rho);   f[1] = pack2(phi, phi); f[2] = pack2(theta, theta);
        f[3] = pack2(ct, ct);     f[4] = pack2(st, st);
        f[5] = pack2(sc, sc);     f[6] = pack2(ss, ss);

        F4U v; v.v = R[9];                      // bias row
        #pragma unroll
        for (int r = 0; r < 7; ++r) {
            F4U m; m.v = R[2 + r];
            v.u[0] = ffma2(f[r], m.u[0], v.u[0]);
            v.u[1] = ffma2(f[r], m.u[1], v.u[1]);
        }
        if (k == 0) v0 = v; else v1 = v;
    }

    // o = w0*v0 + w1*v1 (packed)
    ull w0p = pack2(w0, w0), w1p = pack2(w1, w1);
    F4U o;
    o.u[0] = ffma2(w0p, v0.u[0], fmul2(w1p, v1.u[0]));
    o.u[1] = ffma2(w0p, v0.u[1], fmul2(w1p, v1.u[1]));

    out[i] = o.v;
}

// ---------------------------------------------------------------------------
extern "C" void kernel_launch(void* const* d_in, const int* in_sizes, int n_in,
                              void* d_out, int out_size)
{
    const float* xyzt   = (const float*)d_in[0];
    const float* Wg     = (const float*)d_in[1];
    const float* bg     = (const float*)d_in[2];
    const float* proj   = (const float*)d_in[3];
    const float* center = (const float*)d_in[4];
    const float* tb1    = (const float*)d_in[5];
    const float* tb2    = (const float*)d_in[6];
    const float* W1     = (const float*)d_in[7];
    const float* Wf     = (const float*)d_in[8];
    const float* bf     = (const float*)d_in[9];

    fold_kernel<<<16, 64>>>(Wg, bg, proj, center, tb1, tb2, W1, Wf, bf);
    moe_kernel<<<NPTS / TPB, TPB>>>((const float4*)xyzt, (float4*)d_out);
}

// round 14
// speedup vs baseline: 1.4067x; 1.0622x over previous
#include <cuda_runtime.h>
#include <math.h>

#define NE     16
#define NPTS   524288
#define TPB    256
#define PPT    2
#define NBLK   (NPTS / (TPB * PPT))   // 1024

// Packed parameter blob (196 float4), produced by fold_kernel:
//   [0..15]   gate[e] = {Wg[0][e],Wg[1][e],Wg[2][e],Wg[3][e]}
//   [16..19]  bg (16 floats)
//   [20+e*11] expert record e (float offsets within 44-float record):
//       [0..3]  = cx, cy, cz, tb1
//       [4]     = tb2            ([5..7] pad)
//       [8..35] = M rows (7x4): rho, phi, theta, cos, sin, silu(cos), silu(sin)
//       [36..39]= bias (bf[e])   ([40..43] pad)
__device__ float4 g_R4[196];

// ---------------------------------------------------------------------------
// helpers
// ---------------------------------------------------------------------------
__device__ __forceinline__ float tanh_ap(float x)
{
    float r; asm("tanh.approx.f32 %0, %1;" : "=f"(r) : "f"(x)); return r;
}
__device__ __forceinline__ float fast_sig(float x)   // sigmoid via 1 MUFU
{
    return fmaf(tanh_ap(0.5f * x), 0.5f, 0.5f);
}
__device__ __forceinline__ float fast_sqrt(float x)
{
    float r; asm("sqrt.approx.f32 %0, %1;" : "=f"(r) : "f"(x)); return r;
}

// Branch-free atan2, abs err ~1e-5. theta = atan2(rxy, z) == acos(z/rho).
__device__ __forceinline__ float atan2f_fast(float y, float x)
{
    float ax = fabsf(x), ay = fabsf(y);
    float mx = fmaxf(ax, ay);
    float mn = fminf(ax, ay);
    float a  = __fdividef(mn, mx);
    float s  = a * a;
    float r  = fmaf(s, -0.0117212f, 0.05265332f);
    r = fmaf(s, r, -0.11643287f);
    r = fmaf(s, r,  0.19354346f);
    r = fmaf(s, r, -0.33262347f);
    r = fmaf(s, r,  0.99997726f);
    r = r * a;
    r = (ay > ax) ? 1.57079632679f - r : r;
    r = (x < 0.f) ? 3.14159265359f - r : r;
    return copysignf(r, y);
}

// ---------------------------------------------------------------------------
// Fold kernel: 16 blocks (one expert each) x 64 threads, then PDL trigger.
// ---------------------------------------------------------------------------
__global__ void fold_kernel(const float* __restrict__ Wg,     // (4,16)
                            const float* __restrict__ bg,     // (16)
                            const float* __restrict__ proj,   // (E,3,8)
                            const float* __restrict__ center, // (E,3)
                            const float* __restrict__ tb1,
                            const float* __restrict__ tb2,
                            const float* __restrict__ W1,     // (E,12,32)
                            const float* __restrict__ Wf,     // (E,32,4)
                            const float* __restrict__ bf)     // (E,4)
{
    const int e = blockIdx.x;
    const int t = threadIdx.x;
    __shared__ float sP[48];           // P[p][j] = W1[e,p,:] . Wf[e,:,j]

    if (t < 48) {
        int pi = t >> 2, j = t & 3;
        const float4* W1r = (const float4*)(W1 + (e * 12 + pi) * 32);
        const float*  Wfc = Wf + e * 128 + j;
        float acc = 0.f;
        #pragma unroll
        for (int h4 = 0; h4 < 8; ++h4) {
            float4 a = W1r[h4];
            acc = fmaf(a.x, Wfc[(h4*4+0)*4], acc);
            acc = fmaf(a.y, Wfc[(h4*4+1)*4], acc);
            acc = fmaf(a.z, Wfc[(h4*4+2)*4], acc);
            acc = fmaf(a.w, Wfc[(h4*4+3)*4], acc);
        }
        sP[t] = acc;
    }
    // header (transposed gate + bg), done from spare threads of each block
    if (t == 48) g_R4[e] = make_float4(Wg[e], Wg[16+e], Wg[32+e], Wg[48+e]);
    if (t == 49) ((float*)(g_R4 + 16))[e] = bg[e];
    __syncthreads();

    float* R = (float*)(g_R4 + 20 + e * 11);
    if (t < 12) {                                   // rho/phi/theta rows: fold proj
        int i = t >> 2, j = t & 3;
        const float* pe = proj + e * 24 + i * 8;
        float acc = 0.f;
        #pragma unroll
        for (int p = 0; p < 8; ++p) acc = fmaf(pe[p], sP[p * 4 + j], acc);
        R[8 + i * 4 + j] = acc;
    } else if (t < 28) {                            // temb rows 3..6
        int m = t - 12;
        R[8 + (3 + (m >> 2)) * 4 + (m & 3)] = sP[(8 + (m >> 2)) * 4 + (m & 3)];
    } else if (t < 32) {                            // bias row
        R[36 + (t - 28)] = bf[e * 4 + (t - 28)];
    } else if (t < 35) {                            // center
        R[t - 32] = center[e * 3 + (t - 32)];
    } else if (t == 35) {
        R[3] = tb1[e];
    } else if (t == 36) {
        R[4] = tb2[e];
    }
    // PDL: allow dependent grid to launch; prior stores become visible to its wait
    asm volatile("griddepcontrol.launch_dependents;");
}

// ---------------------------------------------------------------------------
// Main kernel: 2 points per thread, scalar FFMA body, short chains.
// ---------------------------------------------------------------------------
__global__ __launch_bounds__(TPB)
void moe_kernel(const float4* __restrict__ xyzt, float4* __restrict__ out)
{
    asm volatile("griddepcontrol.wait;");

    __shared__ float4 sB[196];
    const int t = threadIdx.x;
    if (t < 196) sB[t] = g_R4[t];
    __syncthreads();

    const float4* gate = sB;
    const float*  sbg  = (const float*)(sB + 16);
    const int base = blockIdx.x * (TPB * PPT) + t;

    float4 pt0 = xyzt[base];
    float4 pt1 = xyzt[base + TPB];

    #pragma unroll
    for (int pp = 0; pp < PPT; ++pp) {
        float4 p = pp ? pt1 : pt0;

        // ---- gating: 16 logits, expert index in low 4 mantissa bits ----
        float l[NE];
        #pragma unroll
        for (int e = 0; e < NE; ++e) {
            float4 g = gate[e];
            float v = fmaf(p.x, g.x, fmaf(p.y, g.y, fmaf(p.z, g.z, fmaf(p.w, g.w, sbg[e]))));
            l[e] = __int_as_float((__float_as_int(v) & 0xFFFFFFF0) | e);
        }
        // pairwise sort (depth 1) + merge tree (3 levels) -> top-2
        float h[8], lo[8];
        #pragma unroll
        for (int i = 0; i < 8; ++i) {
            h[i]  = fmaxf(l[2*i], l[2*i+1]);
            lo[i] = fminf(l[2*i], l[2*i+1]);
        }
        #pragma unroll
        for (int s = 8; s > 1; s >>= 1) {
            #pragma unroll
            for (int i = 0; i < 8; ++i) {
                if (i < (s >> 1)) {
                    float a0 = h[i],        a1 = lo[i];
                    float b0 = h[i+(s>>1)], b1 = lo[i+(s>>1)];
                    float m0 = fmaxf(a0, b0);
                    float ru = (a0 > b0) ? a1 : b1;     // runner-up of winner's pair
                    float m1 = fmaxf(fminf(a0, b0), ru);
                    h[i] = m0; lo[i] = m1;
                }
            }
        }
        float b0 = h[0], b1 = lo[0];
        int e0 = __float_as_int(b0) & 15;
        int e1 = __float_as_int(b1) & 15;
        float w0 = fast_sig(b0 - b1);        // softmax over 2 = sigmoid(diff)

        float4 v0, v1;

        #pragma unroll
        for (int k = 0; k < 2; ++k) {
            int e = k ? e1 : e0;
            const float4* R  = sB + 20 + e * 11;
            const float*  Rf = (const float*)R;

            float4 A   = R[0];               // cx, cy, cz, tb1
            float tb2v = Rf[4];

            float xc0 = p.x - A.x;
            float xc1 = p.y - A.y;
            float xc2 = p.z - A.z;
            float r2xy = fmaf(xc0, xc0, xc1 * xc1);
            float rxy  = fast_sqrt(r2xy);
            float rho  = fast_sqrt(fmaf(xc2, xc2, r2xy));
            float phi   = atan2f_fast(xc1, xc0);
            float theta = atan2f_fast(rxy, xc2);   // == acos(z/rho)

            float ct = __cosf(p.w + A.w);
            float st = __sinf(p.w + tb2v);
            float sc = ct * fast_sig(ct);
            float ss = st * fast_sig(st);

            float4 v = R[9];                 // bias row
            float4 m;
            m = R[2]; v.x=fmaf(rho,  m.x,v.x); v.y=fmaf(rho,  m.y,v.y); v.z=fmaf(rho,  m.z,v.z); v.w=fmaf(rho,  m.w,v.w);
            m = R[3]; v.x=fmaf(phi,  m.x,v.x); v.y=fmaf(phi,  m.y,v.y); v.z=fmaf(phi,  m.z,v.z); v.w=fmaf(phi,  m.w,v.w);
            m = R[4]; v.x=fmaf(theta,m.x,v.x); v.y=fmaf(theta,m.y,v.y); v.z=fmaf(theta,m.z,v.z); v.w=fmaf(theta,m.w,v.w);
            m = R[5]; v.x=fmaf(ct,   m.x,v.x); v.y=fmaf(ct,   m.y,v.y); v.z=fmaf(ct,   m.z,v.z); v.w=fmaf(ct,   m.w,v.w);
            m = R[6]; v.x=fmaf(st,   m.x,v.x); v.y=fmaf(st,   m.y,v.y); v.z=fmaf(st,   m.z,v.z); v.w=fmaf(st,   m.w,v.w);
            m = R[7]; v.x=fmaf(sc,   m.x,v.x); v.y=fmaf(sc,   m.y,v.y); v.z=fmaf(sc,   m.z,v.z); v.w=fmaf(sc,   m.w,v.w);
            m = R[8]; v.x=fmaf(ss,   m.x,v.x); v.y=fmaf(ss,   m.y,v.y); v.z=fmaf(ss,   m.z,v.z); v.w=fmaf(ss,   m.w,v.w);

            if (k == 0) v0 = v; else v1 = v;
        }

        // o = v1 + w0*(v0 - v1)   (uses w0 + w1 = 1)
        float4 o;
        o.x = fmaf(w0, v0.x - v1.x, v1.x);
        o.y = fmaf(w0, v0.y - v1.y, v1.y);
        o.z = fmaf(w0, v0.z - v1.z, v1.z);
        o.w = fmaf(w0, v0.w - v1.w, v1.w);

        out[base + pp * TPB] = o;
    }
}

// ---------------------------------------------------------------------------
extern "C" void kernel_launch(void* const* d_in, const int* in_sizes, int n_in,
                              void* d_out, int out_size)
{
    const float* xyzt   = (const float*)d_in[0];
    const float* Wg     = (const float*)d_in[1];
    const float* bg     = (const float*)d_in[2];
    const float* proj   = (const float*)d_in[3];
    const float* center = (const float*)d_in[4];
    const float* tb1    = (const float*)d_in[5];
    const float* tb2    = (const float*)d_in[6];
    const float* W1     = (const float*)d_in[7];
    const float* Wf     = (const float*)d_in[8];
    const float* bf     = (const float*)d_in[9];

    fold_kernel<<<16, 64>>>(Wg, bg, proj, center, tb1, tb2, W1, Wf, bf);

    // PDL launch: moe_kernel may begin before fold completes; its
    // griddepcontrol.wait blocks until fold's stores are visible.
    cudaLaunchConfig_t cfg = {};
    cfg.gridDim  = dim3(NBLK);
    cfg.blockDim = dim3(TPB);
    cfg.dynamicSmemBytes = 0;
    cfg.stream = 0;
    cudaLaunchAttribute attr[1];
    attr[0].id = cudaLaunchAttributeProgrammaticStreamSerialization;
    attr[0].val.programmaticStreamSerializationAllowed = 1;
    cfg.attrs = attr;
    cfg.numAttrs = 1;
    cudaLaunchKernelEx(&cfg, moe_kernel, (const float4*)xyzt, (float4*)d_out);
}